// round 1
// baseline (speedup 1.0000x reference)
#include <cuda_runtime.h>
#include <math.h>

#define BB 2
#define SS 2048
#define DD 1024
#define HH 16
#define DHD 64
#define GM (BB*SS)   /* 4096 */
#define GN DD        /* 1024 */
#define GK DD        /* 1024 */

// Scratch (allocation-free): Q, K, V, attention-out, each [B*S, D] fp32 (16 MB)
__device__ float g_Q[GM*DD];
__device__ float g_K[GM*DD];
__device__ float g_V[GM*DD];
__device__ float g_AO[GM*DD];

// ---------------------------------------------------------------------------
// SGEMM: C[M,N] = alpha * A[M,K] @ B[N,K]^T   (both A and B are K-major)
// 128x128 block tile, BK=8, 8x8 per thread (split 64+64), 256 threads.
// ---------------------------------------------------------------------------
__global__ __launch_bounds__(256, 2)
void sgemm_nt(const float* __restrict__ A, const float* __restrict__ B,
              float* __restrict__ C, float alpha)
{
    __shared__ float As[8][132];
    __shared__ float Bs[8][132];
    const int tid  = threadIdx.x;
    const int tx   = tid & 15;
    const int ty   = tid >> 4;
    const int cRow = blockIdx.y << 7;
    const int cCol = blockIdx.x << 7;
    const int lr   = tid >> 1;          // 0..127
    const int lk   = (tid & 1) << 2;    // 0 or 4
    const float* Ap = A + (cRow + lr) * GK + lk;
    const float* Bp = B + (cCol + lr) * GK + lk;

    float acc[8][8];
#pragma unroll
    for (int i = 0; i < 8; i++)
#pragma unroll
        for (int j = 0; j < 8; j++) acc[i][j] = 0.f;

    for (int k0 = 0; k0 < GK; k0 += 8) {
        float4 av = *(const float4*)(Ap + k0);
        float4 bv = *(const float4*)(Bp + k0);
        As[lk+0][lr] = av.x; As[lk+1][lr] = av.y;
        As[lk+2][lr] = av.z; As[lk+3][lr] = av.w;
        Bs[lk+0][lr] = bv.x; Bs[lk+1][lr] = bv.y;
        Bs[lk+2][lr] = bv.z; Bs[lk+3][lr] = bv.w;
        __syncthreads();
#pragma unroll
        for (int k = 0; k < 8; k++) {
            float a[8], b[8];
            *(float4*)&a[0] = *(const float4*)&As[k][ty<<2];
            *(float4*)&a[4] = *(const float4*)&As[k][64 + (ty<<2)];
            *(float4*)&b[0] = *(const float4*)&Bs[k][tx<<2];
            *(float4*)&b[4] = *(const float4*)&Bs[k][64 + (tx<<2)];
#pragma unroll
            for (int i = 0; i < 8; i++)
#pragma unroll
                for (int j = 0; j < 8; j++)
                    acc[i][j] += a[i] * b[j];
        }
        __syncthreads();
    }

#pragma unroll
    for (int i = 0; i < 8; i++) {
        int row = cRow + ((i < 4) ? ((ty<<2) + i) : (64 + (ty<<2) + i - 4));
        float4 o0, o1;
        o0.x = acc[i][0]*alpha; o0.y = acc[i][1]*alpha;
        o0.z = acc[i][2]*alpha; o0.w = acc[i][3]*alpha;
        o1.x = acc[i][4]*alpha; o1.y = acc[i][5]*alpha;
        o1.z = acc[i][6]*alpha; o1.w = acc[i][7]*alpha;
        *(float4*)(C + row*GN + cCol + (tx<<2))      = o0;
        *(float4*)(C + row*GN + cCol + 64 + (tx<<2)) = o1;
    }
}

// ---------------------------------------------------------------------------
// Flash attention, causal, fp32. One block per (b, h, 64-row q tile).
// 256 threads as 16x16; each thread owns a 4x4 score microtile and a 4x4
// output microtile. Q/K stored d-major (transposed) in smem so the inner
// product loop uses conflict-free broadcast/stride LDS.128.
// ---------------------------------------------------------------------------
#define FPAD 68

__global__ __launch_bounds__(256, 2)
void flash_attn(const float* __restrict__ Qg, const float* __restrict__ Kg,
                const float* __restrict__ Vg, float* __restrict__ Og)
{
    extern __shared__ float smf[];
    float* QsT = smf;                  // [64][FPAD]  (row = d, col = q-row)
    float* KsT = QsT + 64*FPAD;        // [64][FPAD]  (row = d, col = k-row)
    float* Vs  = KsT + 64*FPAD;        // [64][FPAD]  (row = k-row, col = d)
    float* Ps  = Vs  + 64*FPAD;        // [64][FPAD]  (row = q-row, col = k-col)
    float* red = Ps  + 64*FPAD;        // [64][17]
    float* mS  = red + 64*17;          // [64]
    float* lS  = mS  + 64;             // [64]

    const int qt  = (int)gridDim.x - 1 - (int)blockIdx.x;  // heavy tiles first
    const int h   = blockIdx.y, b = blockIdx.z;
    const int tid = threadIdx.x;
    const int tx  = tid & 15, ty = tid >> 4;
    const int qbase = qt << 6;
    const int hoff  = h << 6;

    // Load Q tile transposed into smem
#pragma unroll
    for (int it = 0; it < 4; it++) {
        int idx = it*256 + tid;
        int r = idx >> 4, d4 = (idx & 15) << 2;
        float4 v = *(const float4*)(Qg + ((b*SS + qbase + r) << 10) + hoff + d4);
        QsT[(d4+0)*FPAD + r] = v.x;
        QsT[(d4+1)*FPAD + r] = v.y;
        QsT[(d4+2)*FPAD + r] = v.z;
        QsT[(d4+3)*FPAD + r] = v.w;
    }
    if (tid < 64) { mS[tid] = -INFINITY; lS[tid] = 0.f; }

    float acc[4][4];
#pragma unroll
    for (int i = 0; i < 4; i++)
#pragma unroll
        for (int j = 0; j < 4; j++) acc[i][j] = 0.f;

    for (int kt = 0; kt <= qt; kt++) {
        __syncthreads();   // protect K/V/Ps reuse + m/l ordering
        const int kbase = kt << 6;
#pragma unroll
        for (int it = 0; it < 4; it++) {
            int idx = it*256 + tid;
            int r = idx >> 4, d4 = (idx & 15) << 2;
            int g = ((b*SS + kbase + r) << 10) + hoff + d4;
            float4 kv = *(const float4*)(Kg + g);
            KsT[(d4+0)*FPAD + r] = kv.x;
            KsT[(d4+1)*FPAD + r] = kv.y;
            KsT[(d4+2)*FPAD + r] = kv.z;
            KsT[(d4+3)*FPAD + r] = kv.w;
            float4 vv = *(const float4*)(Vg + g);
            *(float4*)(Vs + r*FPAD + d4) = vv;
        }
        __syncthreads();

        // scores: s[i][j] = q_row(4ty+i) . k_row(4tx+j)   (q already scaled)
        float s[4][4];
#pragma unroll
        for (int i = 0; i < 4; i++)
#pragma unroll
            for (int j = 0; j < 4; j++) s[i][j] = 0.f;
#pragma unroll
        for (int d = 0; d < 64; d++) {
            float4 qv = *(const float4*)(QsT + d*FPAD + (ty<<2));
            float4 kv = *(const float4*)(KsT + d*FPAD + (tx<<2));
            float qa[4] = {qv.x, qv.y, qv.z, qv.w};
            float ka[4] = {kv.x, kv.y, kv.z, kv.w};
#pragma unroll
            for (int i = 0; i < 4; i++)
#pragma unroll
                for (int j = 0; j < 4; j++)
                    s[i][j] += qa[i] * ka[j];
        }
        if (kt == qt) {
#pragma unroll
            for (int i = 0; i < 4; i++)
#pragma unroll
                for (int j = 0; j < 4; j++)
                    if (kbase + (tx<<2) + j > qbase + (ty<<2) + i)
                        s[i][j] = -1e10f;   // matches reference bias; exp -> 0
        }

        // row-max partials
#pragma unroll
        for (int i = 0; i < 4; i++) {
            float pm = fmaxf(fmaxf(s[i][0], s[i][1]), fmaxf(s[i][2], s[i][3]));
            red[((ty<<2)+i)*17 + tx] = pm;
        }
        __syncthreads();

        float mnew[4], corr[4], psum[4];
#pragma unroll
        for (int i = 0; i < 4; i++) {
            int r = (ty<<2) + i;
            float rm = red[r*17];
#pragma unroll
            for (int t = 1; t < 16; t++) rm = fmaxf(rm, red[r*17 + t]);
            float mo = mS[r];
            float mn = fmaxf(mo, rm);
            mnew[i] = mn;
            corr[i] = __expf(mo - mn);   // exp(-inf) = 0 on first tile
            psum[i] = 0.f;
#pragma unroll
            for (int j = 0; j < 4; j++) {
                float p = __expf(s[i][j] - mn);
                Ps[r*FPAD + (tx<<2) + j] = p;
                psum[i] += p;
            }
#pragma unroll
            for (int j = 0; j < 4; j++) acc[i][j] *= corr[i];
        }
        __syncthreads();   // red(max) reads done; Ps fully written

#pragma unroll
        for (int i = 0; i < 4; i++)
            red[((ty<<2)+i)*17 + tx] = psum[i];
        __syncthreads();

#pragma unroll
        for (int i = 0; i < 4; i++) {
            if (tx == 0) {
                int r = (ty<<2) + i;
                float rs = 0.f;
#pragma unroll
                for (int t = 0; t < 16; t++) rs += red[r*17 + t];
                lS[r] = lS[r]*corr[i] + rs;
                mS[r] = mnew[i];
            }
        }

        // O += P @ V
#pragma unroll
        for (int c = 0; c < 64; c++) {
            float4 vv = *(const float4*)(Vs + c*FPAD + (tx<<2));
            float va[4] = {vv.x, vv.y, vv.z, vv.w};
#pragma unroll
            for (int i = 0; i < 4; i++) {
                float p = Ps[((ty<<2)+i)*FPAD + c];
#pragma unroll
                for (int j = 0; j < 4; j++) acc[i][j] += p * va[j];
            }
        }
    }

    __syncthreads();  // lS final
#pragma unroll
    for (int i = 0; i < 4; i++) {
        int r = (ty<<2) + i;
        float inv = 1.f / lS[r];
        float4 o;
        o.x = acc[i][0]*inv; o.y = acc[i][1]*inv;
        o.z = acc[i][2]*inv; o.w = acc[i][3]*inv;
        *(float4*)(Og + ((b*SS + qbase + r) << 10) + hoff + (tx<<2)) = o;
    }
}

// ---------------------------------------------------------------------------
extern "C" void kernel_launch(void* const* d_in, const int* in_sizes, int n_in,
                              void* d_out, int out_size)
{
    (void)in_sizes; (void)n_in; (void)out_size;
    const float* X  = (const float*)d_in[0];
    const float* Wq = (const float*)d_in[1];
    const float* Wk = (const float*)d_in[2];
    const float* Wv = (const float*)d_in[3];
    const float* Wo = (const float*)d_in[4];
    float* out = (float*)d_out;

    float *Qb, *Kb, *Vb, *AOb;
    cudaGetSymbolAddress((void**)&Qb,  g_Q);
    cudaGetSymbolAddress((void**)&Kb,  g_K);
    cudaGetSymbolAddress((void**)&Vb,  g_V);
    cudaGetSymbolAddress((void**)&AOb, g_AO);

    const int flash_smem = (4*64*FPAD + 64*17 + 128) * (int)sizeof(float); // ~74.5 KB
    cudaFuncSetAttribute(flash_attn, cudaFuncAttributeMaxDynamicSharedMemorySize,
                         flash_smem);

    dim3 gg(GN/128, GM/128);  // (8, 32)
    sgemm_nt<<<gg, 256>>>(X, Wq, Qb, 0.125f);   // DH^-0.5 fused into Q
    sgemm_nt<<<gg, 256>>>(X, Wk, Kb, 1.0f);
    sgemm_nt<<<gg, 256>>>(X, Wv, Vb, 1.0f);
    flash_attn<<<dim3(SS/64, HH, BB), 256, flash_smem>>>(Qb, Kb, Vb, AOb);
    sgemm_nt<<<gg, 256>>>(AOb, Wo, out, 1.0f);
}

// round 3
// speedup vs baseline: 1.4872x; 1.4872x over previous
#include <cuda_runtime.h>
#include <cuda_bf16.h>
#include <math.h>
#include <stdint.h>

#define BB 2
#define SS 2048
#define DD 1024
#define HH 16
#define GM (BB*SS)   /* 4096 */
#define GN DD        /* 1024 */
#define GK DD        /* 1024 */

// ---------------- scratch (allocation-free) ----------------
__device__ float g_Q[GM*DD];
__device__ float g_K[GM*DD];
__device__ float g_V[GM*DD];
__device__ float g_AO[GM*DD];
__device__ __nv_bfloat16 g_Xh[GM*DD],  g_Xl[GM*DD];
__device__ __nv_bfloat16 g_AOh[GM*DD], g_AOl[GM*DD];
__device__ __nv_bfloat16 g_Wqh[DD*DD], g_Wql[DD*DD];
__device__ __nv_bfloat16 g_Wkh[DD*DD], g_Wkl[DD*DD];
__device__ __nv_bfloat16 g_Wvh[DD*DD], g_Wvl[DD*DD];
__device__ __nv_bfloat16 g_Woh[DD*DD], g_Wol[DD*DD];

// ---------------- helpers ----------------
__device__ __forceinline__ uint32_t smem_u32(const void* p) {
    return (uint32_t)__cvta_generic_to_shared(p);
}
__device__ __forceinline__ void cp_async16(uint32_t dst, const void* src) {
    asm volatile("cp.async.cg.shared.global [%0], [%1], 16;" :: "r"(dst), "l"(src) : "memory");
}
__device__ __forceinline__ void cp_commit() {
    asm volatile("cp.async.commit_group;" ::: "memory");
}
template<int N>
__device__ __forceinline__ void cp_wait() {
    asm volatile("cp.async.wait_group %0;" :: "n"(N) : "memory");
}
__device__ __forceinline__ void ldm_x4(uint32_t* r, uint32_t addr) {
    asm volatile("ldmatrix.sync.aligned.m8n8.x4.shared.b16 {%0,%1,%2,%3}, [%4];"
                 : "=r"(r[0]), "=r"(r[1]), "=r"(r[2]), "=r"(r[3]) : "r"(addr));
}
__device__ __forceinline__ void mma_bf16(float* c, const uint32_t* a, const uint32_t* b) {
    asm volatile("mma.sync.aligned.m16n8k16.row.col.f32.bf16.bf16.f32 "
                 "{%0,%1,%2,%3}, {%4,%5,%6,%7}, {%8,%9}, {%0,%1,%2,%3};"
                 : "+f"(c[0]), "+f"(c[1]), "+f"(c[2]), "+f"(c[3])
                 : "r"(a[0]), "r"(a[1]), "r"(a[2]), "r"(a[3]), "r"(b[0]), "r"(b[1]));
}

// ---------------- split fp32 -> bf16 hi/lo ----------------
__global__ void split_bf16(const float* __restrict__ in, __nv_bfloat16* __restrict__ hi,
                           __nv_bfloat16* __restrict__ lo, int n4)
{
    int i = blockIdx.x*blockDim.x + threadIdx.x;
    int stride = gridDim.x*blockDim.x;
    const float4* in4 = (const float4*)in;
    __nv_bfloat162* h2 = (__nv_bfloat162*)hi;
    __nv_bfloat162* l2 = (__nv_bfloat162*)lo;
    for (; i < n4; i += stride) {
        float4 v = in4[i];
        __nv_bfloat16 a0 = __float2bfloat16(v.x);
        __nv_bfloat16 a1 = __float2bfloat16(v.y);
        __nv_bfloat16 a2 = __float2bfloat16(v.z);
        __nv_bfloat16 a3 = __float2bfloat16(v.w);
        __nv_bfloat16 b0 = __float2bfloat16(v.x - __bfloat162float(a0));
        __nv_bfloat16 b1 = __float2bfloat16(v.y - __bfloat162float(a1));
        __nv_bfloat16 b2 = __float2bfloat16(v.z - __bfloat162float(a2));
        __nv_bfloat16 b3 = __float2bfloat16(v.w - __bfloat162float(a3));
        h2[i*2]   = __halves2bfloat162(a0, a1);
        h2[i*2+1] = __halves2bfloat162(a2, a3);
        l2[i*2]   = __halves2bfloat162(b0, b1);
        l2[i*2+1] = __halves2bfloat162(b2, b3);
    }
}

// ---------------- bf16x2 GEMM on mma.sync: C = alpha * (A @ B^T) ----------------
// A[M,K], B[N,K] hi/lo bf16; C fp32. CTA tile 128x128, K-chunk 64, 2-stage cp.async.
#define KCH 64
#define NCH (GK/KCH)       /* 16 */
#define SRE 72             /* smem row stride, bf16 elements */
#define SRB (SRE*2)        /* 144 bytes */
#define TILE_B (128*SRB)   /* 18432 bytes */
#define STAGE_B (4*TILE_B) /* Ah, Al, Bh, Bl */
#define GEMM_SMEM (2*STAGE_B) /* 147456 */

__global__ __launch_bounds__(256, 1)
void gemm_bf16x2(const __nv_bfloat16* __restrict__ Ah, const __nv_bfloat16* __restrict__ Al,
                 const __nv_bfloat16* __restrict__ Bh, const __nv_bfloat16* __restrict__ Bl,
                 float* __restrict__ C, float alpha)
{
    extern __shared__ char smem[];
    const uint32_t sb = smem_u32(smem);
    const int tid  = threadIdx.x;
    const int lane = tid & 31;
    const int warp = tid >> 5;
    const int wm   = warp & 3;        // M warp (0..3) -> 32 rows each
    const int wn   = warp >> 2;       // N warp (0..1) -> 64 cols each
    const int cRow = blockIdx.y << 7;
    const int cCol = blockIdx.x << 7;

    // global bases for the 4 tiles (A rows at cRow, B rows at cCol)
    const __nv_bfloat16* gsrc[4];
    gsrc[0] = Ah + (size_t)cRow*GK;
    gsrc[1] = Al + (size_t)cRow*GK;
    gsrc[2] = Bh + (size_t)cCol*GK;
    gsrc[3] = Bl + (size_t)cCol*GK;

    const int ldRow = tid >> 3;       // 0..31 (x4 iterations of +32)
    const int ldCol = tid & 7;        // 16B column

    // ldmatrix per-lane offsets (bytes, within a tile)
    const uint32_t aOff = (uint32_t)((lane & 15)*SRB + (lane >> 4)*16 + wm*32*SRB);
    const uint32_t bOff = (uint32_t)(((lane & 7) + ((lane >> 4) << 3))*SRB
                                     + ((lane >> 3) & 1)*16 + wn*64*SRB);

    float acc[2][8][4];
#pragma unroll
    for (int mt = 0; mt < 2; mt++)
#pragma unroll
        for (int nt = 0; nt < 8; nt++)
#pragma unroll
            for (int q = 0; q < 4; q++) acc[mt][nt][q] = 0.f;

    // ---- prologue: load chunk 0 ----
#pragma unroll
    for (int t = 0; t < 4; t++)
#pragma unroll
        for (int i = 0; i < 4; i++) {
            int row = ldRow + i*32;
            cp_async16(sb + t*TILE_B + row*SRB + ldCol*16,
                       gsrc[t] + (size_t)row*GK + ldCol*8);
        }
    cp_commit();

    for (int j = 0; j < NCH; j++) {
        if (j + 1 < NCH) {
            const uint32_t st = sb + ((j+1) & 1)*STAGE_B;
            const int k0 = (j+1)*KCH;
#pragma unroll
            for (int t = 0; t < 4; t++)
#pragma unroll
                for (int i = 0; i < 4; i++) {
                    int row = ldRow + i*32;
                    cp_async16(st + t*TILE_B + row*SRB + ldCol*16,
                               gsrc[t] + (size_t)row*GK + k0 + ldCol*8);
                }
            cp_commit();
            cp_wait<1>();
        } else {
            cp_wait<0>();
        }
        __syncthreads();

        const uint32_t stg = sb + (j & 1)*STAGE_B;
        // splits: (Ah,Bh), (Ah,Bl), (Al,Bh)
#pragma unroll
        for (int sp = 0; sp < 3; sp++) {
            const uint32_t aBase = stg + ((sp == 2) ? TILE_B : 0) + aOff;
            const uint32_t bBase = stg + ((sp == 1) ? 3*TILE_B : 2*TILE_B) + bOff;
#pragma unroll
            for (int k16 = 0; k16 < 4; k16++) {
                uint32_t a[2][4], b[4][4];
                ldm_x4(a[0], aBase + k16*32);
                ldm_x4(a[1], aBase + k16*32 + 16*SRB);
#pragma unroll
                for (int ng = 0; ng < 4; ng++)
                    ldm_x4(b[ng], bBase + k16*32 + ng*16*SRB);
#pragma unroll
                for (int mt = 0; mt < 2; mt++)
#pragma unroll
                    for (int ng = 0; ng < 4; ng++) {
                        mma_bf16(acc[mt][2*ng+0], a[mt], &b[ng][0]);
                        mma_bf16(acc[mt][2*ng+1], a[mt], &b[ng][2]);
                    }
            }
        }
        __syncthreads();
    }

    // ---- epilogue ----
    const int gid = lane >> 2, tig = lane & 3;
#pragma unroll
    for (int mt = 0; mt < 2; mt++) {
        const int m0 = cRow + wm*32 + mt*16 + gid;
#pragma unroll
        for (int nt = 0; nt < 8; nt++) {
            const int n = cCol + wn*64 + nt*8 + tig*2;
            float2 v0 = { acc[mt][nt][0]*alpha, acc[mt][nt][1]*alpha };
            float2 v1 = { acc[mt][nt][2]*alpha, acc[mt][nt][3]*alpha };
            *(float2*)(C + (size_t)m0*GN + n)     = v0;
            *(float2*)(C + (size_t)(m0+8)*GN + n) = v1;
        }
    }
}

// ---------------------------------------------------------------------------
// Flash attention, causal, fp32 (unchanged from R1 passing version).
// ---------------------------------------------------------------------------
#define FPAD 68

__global__ __launch_bounds__(256, 2)
void flash_attn(const float* __restrict__ Qg, const float* __restrict__ Kg,
                const float* __restrict__ Vg, float* __restrict__ Og)
{
    extern __shared__ float smf[];
    float* QsT = smf;
    float* KsT = QsT + 64*FPAD;
    float* Vs  = KsT + 64*FPAD;
    float* Ps  = Vs  + 64*FPAD;
    float* red = Ps  + 64*FPAD;
    float* mS  = red + 64*17;
    float* lS  = mS  + 64;

    const int qt  = (int)gridDim.x - 1 - (int)blockIdx.x;
    const int h   = blockIdx.y, b = blockIdx.z;
    const int tid = threadIdx.x;
    const int tx  = tid & 15, ty = tid >> 4;
    const int qbase = qt << 6;
    const int hoff  = h << 6;

#pragma unroll
    for (int it = 0; it < 4; it++) {
        int idx = it*256 + tid;
        int r = idx >> 4, d4 = (idx & 15) << 2;
        float4 v = *(const float4*)(Qg + ((b*SS + qbase + r) << 10) + hoff + d4);
        QsT[(d4+0)*FPAD + r] = v.x;
        QsT[(d4+1)*FPAD + r] = v.y;
        QsT[(d4+2)*FPAD + r] = v.z;
        QsT[(d4+3)*FPAD + r] = v.w;
    }
    if (tid < 64) { mS[tid] = -INFINITY; lS[tid] = 0.f; }

    float acc[4][4];
#pragma unroll
    for (int i = 0; i < 4; i++)
#pragma unroll
        for (int j = 0; j < 4; j++) acc[i][j] = 0.f;

    for (int kt = 0; kt <= qt; kt++) {
        __syncthreads();
        const int kbase = kt << 6;
#pragma unroll
        for (int it = 0; it < 4; it++) {
            int idx = it*256 + tid;
            int r = idx >> 4, d4 = (idx & 15) << 2;
            int g = ((b*SS + kbase + r) << 10) + hoff + d4;
            float4 kv = *(const float4*)(Kg + g);
            KsT[(d4+0)*FPAD + r] = kv.x;
            KsT[(d4+1)*FPAD + r] = kv.y;
            KsT[(d4+2)*FPAD + r] = kv.z;
            KsT[(d4+3)*FPAD + r] = kv.w;
            float4 vv = *(const float4*)(Vg + g);
            *(float4*)(Vs + r*FPAD + d4) = vv;
        }
        __syncthreads();

        float s[4][4];
#pragma unroll
        for (int i = 0; i < 4; i++)
#pragma unroll
            for (int j = 0; j < 4; j++) s[i][j] = 0.f;
#pragma unroll
        for (int d = 0; d < 64; d++) {
            float4 qv = *(const float4*)(QsT + d*FPAD + (ty<<2));
            float4 kv = *(const float4*)(KsT + d*FPAD + (tx<<2));
            float qa[4] = {qv.x, qv.y, qv.z, qv.w};
            float ka[4] = {kv.x, kv.y, kv.z, kv.w};
#pragma unroll
            for (int i = 0; i < 4; i++)
#pragma unroll
                for (int j = 0; j < 4; j++)
                    s[i][j] += qa[i] * ka[j];
        }
        if (kt == qt) {
#pragma unroll
            for (int i = 0; i < 4; i++)
#pragma unroll
                for (int j = 0; j < 4; j++)
                    if (kbase + (tx<<2) + j > qbase + (ty<<2) + i)
                        s[i][j] = -1e10f;
        }

#pragma unroll
        for (int i = 0; i < 4; i++) {
            float pm = fmaxf(fmaxf(s[i][0], s[i][1]), fmaxf(s[i][2], s[i][3]));
            red[((ty<<2)+i)*17 + tx] = pm;
        }
        __syncthreads();

        float mnew[4], corr[4], psum[4];
#pragma unroll
        for (int i = 0; i < 4; i++) {
            int r = (ty<<2) + i;
            float rm = red[r*17];
#pragma unroll
            for (int t = 1; t < 16; t++) rm = fmaxf(rm, red[r*17 + t]);
            float mo = mS[r];
            float mn = fmaxf(mo, rm);
            mnew[i] = mn;
            corr[i] = __expf(mo - mn);
            psum[i] = 0.f;
#pragma unroll
            for (int j = 0; j < 4; j++) {
                float p = __expf(s[i][j] - mn);
                Ps[r*FPAD + (tx<<2) + j] = p;
                psum[i] += p;
            }
#pragma unroll
            for (int j = 0; j < 4; j++) acc[i][j] *= corr[i];
        }
        __syncthreads();

#pragma unroll
        for (int i = 0; i < 4; i++)
            red[((ty<<2)+i)*17 + tx] = psum[i];
        __syncthreads();

#pragma unroll
        for (int i = 0; i < 4; i++) {
            if (tx == 0) {
                int r = (ty<<2) + i;
                float rs = 0.f;
#pragma unroll
                for (int t = 0; t < 16; t++) rs += red[r*17 + t];
                lS[r] = lS[r]*corr[i] + rs;
                mS[r] = mnew[i];
            }
        }

#pragma unroll
        for (int c = 0; c < 64; c++) {
            float4 vv = *(const float4*)(Vs + c*FPAD + (tx<<2));
            float va[4] = {vv.x, vv.y, vv.z, vv.w};
#pragma unroll
            for (int i = 0; i < 4; i++) {
                float p = Ps[((ty<<2)+i)*FPAD + c];
#pragma unroll
                for (int j = 0; j < 4; j++) acc[i][j] += p * va[j];
            }
        }
    }

    __syncthreads();
#pragma unroll
    for (int i = 0; i < 4; i++) {
        int r = (ty<<2) + i;
        float inv = 1.f / lS[r];
        float4 o;
        o.x = acc[i][0]*inv; o.y = acc[i][1]*inv;
        o.z = acc[i][2]*inv; o.w = acc[i][3]*inv;
        *(float4*)(Og + ((b*SS + qbase + r) << 10) + hoff + (tx<<2)) = o;
    }
}

// ---------------------------------------------------------------------------
extern "C" void kernel_launch(void* const* d_in, const int* in_sizes, int n_in,
                              void* d_out, int out_size)
{
    (void)in_sizes; (void)n_in; (void)out_size;
    const float* X  = (const float*)d_in[0];
    const float* Wq = (const float*)d_in[1];
    const float* Wk = (const float*)d_in[2];
    const float* Wv = (const float*)d_in[3];
    const float* Wo = (const float*)d_in[4];
    float* out = (float*)d_out;

    float *Qb, *Kb, *Vb, *AOb;
    __nv_bfloat16 *Xh, *Xl, *AOh, *AOl;
    __nv_bfloat16 *Wqh, *Wql, *Wkh, *Wkl, *Wvh, *Wvl, *Woh, *Wol;
    cudaGetSymbolAddress((void**)&Qb,  g_Q);
    cudaGetSymbolAddress((void**)&Kb,  g_K);
    cudaGetSymbolAddress((void**)&Vb,  g_V);
    cudaGetSymbolAddress((void**)&AOb, g_AO);
    cudaGetSymbolAddress((void**)&Xh,  g_Xh);
    cudaGetSymbolAddress((void**)&Xl,  g_Xl);
    cudaGetSymbolAddress((void**)&AOh, g_AOh);
    cudaGetSymbolAddress((void**)&AOl, g_AOl);
    cudaGetSymbolAddress((void**)&Wqh, g_Wqh);
    cudaGetSymbolAddress((void**)&Wql, g_Wql);
    cudaGetSymbolAddress((void**)&Wkh, g_Wkh);
    cudaGetSymbolAddress((void**)&Wkl, g_Wkl);
    cudaGetSymbolAddress((void**)&Wvh, g_Wvh);
    cudaGetSymbolAddress((void**)&Wvl, g_Wvl);
    cudaGetSymbolAddress((void**)&Woh, g_Woh);
    cudaGetSymbolAddress((void**)&Wol, g_Wol);

    const int flash_smem = (4*64*FPAD + 64*17 + 128) * (int)sizeof(float);
    cudaFuncSetAttribute(flash_attn, cudaFuncAttributeMaxDynamicSharedMemorySize, flash_smem);
    cudaFuncSetAttribute(gemm_bf16x2, cudaFuncAttributeMaxDynamicSharedMemorySize, GEMM_SMEM);

    split_bf16<<<512, 256>>>(X,  Xh,  Xl,  GM*DD/4);
    split_bf16<<<256, 256>>>(Wq, Wqh, Wql, DD*DD/4);
    split_bf16<<<256, 256>>>(Wk, Wkh, Wkl, DD*DD/4);
    split_bf16<<<256, 256>>>(Wv, Wvh, Wvl, DD*DD/4);
    split_bf16<<<256, 256>>>(Wo, Woh, Wol, DD*DD/4);

    dim3 gg(GN/128, GM/128);   // (8, 32) = 256 CTAs
    gemm_bf16x2<<<gg, 256, GEMM_SMEM>>>(Xh, Xl, Wqh, Wql, Qb, 0.125f);
    gemm_bf16x2<<<gg, 256, GEMM_SMEM>>>(Xh, Xl, Wkh, Wkl, Kb, 1.0f);
    gemm_bf16x2<<<gg, 256, GEMM_SMEM>>>(Xh, Xl, Wvh, Wvl, Vb, 1.0f);

    flash_attn<<<dim3(SS/64, HH, BB), 256, flash_smem>>>(Qb, Kb, Vb, AOb);

    split_bf16<<<512, 256>>>(AOb, AOh, AOl, GM*DD/4);
    gemm_bf16x2<<<gg, 256, GEMM_SMEM>>>(AOh, AOl, Woh, Wol, out, 1.0f);
}

// round 4
// speedup vs baseline: 2.6520x; 1.7832x over previous
#include <cuda_runtime.h>
#include <cuda_bf16.h>
#include <math.h>
#include <stdint.h>

#define BB 2
#define SS 2048
#define DD 1024
#define HH 16
#define GM (BB*SS)   /* 4096 */
#define GN DD
#define GK DD

// ---------------- scratch (allocation-free) ----------------
__device__ __nv_bfloat16 g_Xh[GM*DD],  g_Xl[GM*DD];
__device__ __nv_bfloat16 g_Qh[GM*DD],  g_Ql[GM*DD];
__device__ __nv_bfloat16 g_Kh[GM*DD],  g_Kl[GM*DD];
__device__ __nv_bfloat16 g_Vh[GM*DD],  g_Vl[GM*DD];
__device__ __nv_bfloat16 g_AOh[GM*DD], g_AOl[GM*DD];
__device__ __nv_bfloat16 g_Wqh[DD*DD], g_Wql[DD*DD];
__device__ __nv_bfloat16 g_Wkh[DD*DD], g_Wkl[DD*DD];
__device__ __nv_bfloat16 g_Wvh[DD*DD], g_Wvl[DD*DD];
__device__ __nv_bfloat16 g_Woh[DD*DD], g_Wol[DD*DD];

// ---------------- helpers ----------------
__device__ __forceinline__ uint32_t smem_u32(const void* p) {
    return (uint32_t)__cvta_generic_to_shared(p);
}
__device__ __forceinline__ void cp_async16(uint32_t dst, const void* src) {
    asm volatile("cp.async.cg.shared.global [%0], [%1], 16;" :: "r"(dst), "l"(src) : "memory");
}
__device__ __forceinline__ void cp_commit() {
    asm volatile("cp.async.commit_group;" ::: "memory");
}
template<int N>
__device__ __forceinline__ void cp_wait() {
    asm volatile("cp.async.wait_group %0;" :: "n"(N) : "memory");
}
__device__ __forceinline__ void ldm_x4(uint32_t* r, uint32_t addr) {
    asm volatile("ldmatrix.sync.aligned.m8n8.x4.shared.b16 {%0,%1,%2,%3}, [%4];"
                 : "=r"(r[0]), "=r"(r[1]), "=r"(r[2]), "=r"(r[3]) : "r"(addr));
}
__device__ __forceinline__ void ldm_x4_t(uint32_t* r, uint32_t addr) {
    asm volatile("ldmatrix.sync.aligned.m8n8.x4.trans.shared.b16 {%0,%1,%2,%3}, [%4];"
                 : "=r"(r[0]), "=r"(r[1]), "=r"(r[2]), "=r"(r[3]) : "r"(addr));
}
__device__ __forceinline__ void mma_bf16(float* c, const uint32_t* a, const uint32_t* b) {
    asm volatile("mma.sync.aligned.m16n8k16.row.col.f32.bf16.bf16.f32 "
                 "{%0,%1,%2,%3}, {%4,%5,%6,%7}, {%8,%9}, {%0,%1,%2,%3};"
                 : "+f"(c[0]), "+f"(c[1]), "+f"(c[2]), "+f"(c[3])
                 : "r"(a[0]), "r"(a[1]), "r"(a[2]), "r"(a[3]), "r"(b[0]), "r"(b[1]));
}
__device__ __forceinline__ uint32_t packbf(float lo, float hi) {
    uint32_t r; asm("cvt.rn.bf16x2.f32 %0, %1, %2;" : "=r"(r) : "f"(hi), "f"(lo)); return r;
}
__device__ __forceinline__ float bflo(uint32_t r) { return __uint_as_float(r << 16); }
__device__ __forceinline__ float bfhi(uint32_t r) { return __uint_as_float(r & 0xffff0000u); }
__device__ __forceinline__ float warp_rmax(float x) {
    x = fmaxf(x, __shfl_xor_sync(0xffffffffu, x, 1));
    x = fmaxf(x, __shfl_xor_sync(0xffffffffu, x, 2));
    return x;
}
__device__ __forceinline__ float warp_rsum(float x) {
    x += __shfl_xor_sync(0xffffffffu, x, 1);
    x += __shfl_xor_sync(0xffffffffu, x, 2);
    return x;
}

// ---------------- split fp32 -> bf16 hi/lo (X and weights only) ----------------
__global__ void split_bf16(const float* __restrict__ in, __nv_bfloat16* __restrict__ hi,
                           __nv_bfloat16* __restrict__ lo, int n4)
{
    int i = blockIdx.x*blockDim.x + threadIdx.x;
    int stride = gridDim.x*blockDim.x;
    const float4* in4 = (const float4*)in;
    uint32_t* h2 = (uint32_t*)hi;
    uint32_t* l2 = (uint32_t*)lo;
    for (; i < n4; i += stride) {
        float4 v = in4[i];
        uint32_t h01 = packbf(v.x, v.y), h23 = packbf(v.z, v.w);
        uint32_t l01 = packbf(v.x - bflo(h01), v.y - bfhi(h01));
        uint32_t l23 = packbf(v.z - bflo(h23), v.w - bfhi(h23));
        h2[i*2] = h01; h2[i*2+1] = h23;
        l2[i*2] = l01; l2[i*2+1] = l23;
    }
}

// ---------------- bf16x2 GEMM on mma.sync: C = alpha * (A @ B^T) ----------------
#define KCH 64
#define NCH (GK/KCH)
#define SRE 72
#define SRB (SRE*2)
#define TILE_B (128*SRB)
#define STAGE_B (4*TILE_B)
#define GEMM_SMEM (2*STAGE_B)

template<bool SPLIT>
__global__ __launch_bounds__(256, 1)
void gemm_bf16x2(const __nv_bfloat16* __restrict__ Ah, const __nv_bfloat16* __restrict__ Al,
                 const __nv_bfloat16* __restrict__ Bh, const __nv_bfloat16* __restrict__ Bl,
                 float* __restrict__ Cf, __nv_bfloat16* __restrict__ Chi,
                 __nv_bfloat16* __restrict__ Clo, float alpha)
{
    extern __shared__ char smem[];
    const uint32_t sb = smem_u32(smem);
    const int tid  = threadIdx.x;
    const int lane = tid & 31;
    const int warp = tid >> 5;
    const int wm   = warp & 3;
    const int wn   = warp >> 2;
    const int cRow = blockIdx.y << 7;
    const int cCol = blockIdx.x << 7;

    const __nv_bfloat16* gsrc[4];
    gsrc[0] = Ah + (size_t)cRow*GK;
    gsrc[1] = Al + (size_t)cRow*GK;
    gsrc[2] = Bh + (size_t)cCol*GK;
    gsrc[3] = Bl + (size_t)cCol*GK;

    const int ldRow = tid >> 3;
    const int ldCol = tid & 7;

    const uint32_t aOff = (uint32_t)((lane & 15)*SRB + (lane >> 4)*16 + wm*32*SRB);
    const uint32_t bOff = (uint32_t)(((lane & 7) + ((lane >> 4) << 3))*SRB
                                     + ((lane >> 3) & 1)*16 + wn*64*SRB);

    float acc[2][8][4];
#pragma unroll
    for (int mt = 0; mt < 2; mt++)
#pragma unroll
        for (int nt = 0; nt < 8; nt++)
#pragma unroll
            for (int q = 0; q < 4; q++) acc[mt][nt][q] = 0.f;

#pragma unroll
    for (int t = 0; t < 4; t++)
#pragma unroll
        for (int i = 0; i < 4; i++) {
            int row = ldRow + i*32;
            cp_async16(sb + t*TILE_B + row*SRB + ldCol*16,
                       gsrc[t] + (size_t)row*GK + ldCol*8);
        }
    cp_commit();

    for (int j = 0; j < NCH; j++) {
        if (j + 1 < NCH) {
            const uint32_t st = sb + ((j+1) & 1)*STAGE_B;
            const int k0 = (j+1)*KCH;
#pragma unroll
            for (int t = 0; t < 4; t++)
#pragma unroll
                for (int i = 0; i < 4; i++) {
                    int row = ldRow + i*32;
                    cp_async16(st + t*TILE_B + row*SRB + ldCol*16,
                               gsrc[t] + (size_t)row*GK + k0 + ldCol*8);
                }
            cp_commit();
            cp_wait<1>();
        } else {
            cp_wait<0>();
        }
        __syncthreads();

        const uint32_t stg = sb + (j & 1)*STAGE_B;
#pragma unroll
        for (int sp = 0; sp < 3; sp++) {
            const uint32_t aBase = stg + ((sp == 2) ? TILE_B : 0) + aOff;
            const uint32_t bBase = stg + ((sp == 1) ? 3*TILE_B : 2*TILE_B) + bOff;
#pragma unroll
            for (int k16 = 0; k16 < 4; k16++) {
                uint32_t a[2][4], b[4][4];
                ldm_x4(a[0], aBase + k16*32);
                ldm_x4(a[1], aBase + k16*32 + 16*SRB);
#pragma unroll
                for (int ng = 0; ng < 4; ng++)
                    ldm_x4(b[ng], bBase + k16*32 + ng*16*SRB);
#pragma unroll
                for (int mt = 0; mt < 2; mt++)
#pragma unroll
                    for (int ng = 0; ng < 4; ng++) {
                        mma_bf16(acc[mt][2*ng+0], a[mt], &b[ng][0]);
                        mma_bf16(acc[mt][2*ng+1], a[mt], &b[ng][2]);
                    }
            }
        }
        __syncthreads();
    }

    const int gid = lane >> 2, tig = lane & 3;
#pragma unroll
    for (int mt = 0; mt < 2; mt++) {
        const int m0 = cRow + wm*32 + mt*16 + gid;
#pragma unroll
        for (int nt = 0; nt < 8; nt++) {
            const int n = cCol + wn*64 + nt*8 + tig*2;
            float v0 = acc[mt][nt][0]*alpha, v1 = acc[mt][nt][1]*alpha;
            float v2 = acc[mt][nt][2]*alpha, v3 = acc[mt][nt][3]*alpha;
            if (SPLIT) {
                uint32_t h01 = packbf(v0, v1), h23 = packbf(v2, v3);
                uint32_t l01 = packbf(v0 - bflo(h01), v1 - bfhi(h01));
                uint32_t l23 = packbf(v2 - bflo(h23), v3 - bfhi(h23));
                *(uint32_t*)(Chi + (size_t)m0*GN + n)     = h01;
                *(uint32_t*)(Clo + (size_t)m0*GN + n)     = l01;
                *(uint32_t*)(Chi + (size_t)(m0+8)*GN + n) = h23;
                *(uint32_t*)(Clo + (size_t)(m0+8)*GN + n) = l23;
            } else {
                float2 a0 = {v0, v1}, a1 = {v2, v3};
                *(float2*)(Cf + (size_t)m0*GN + n)     = a0;
                *(float2*)(Cf + (size_t)(m0+8)*GN + n) = a1;
            }
        }
    }
}

// ---------------------------------------------------------------------------
// Flash attention on mma.sync, causal, bf16x2 split precision.
// CTA: 128 q-rows, 8 warps (16 rows/warp), k-tiles of 64, double-buffered.
// ---------------------------------------------------------------------------
#define FQSTR 72                       /* halves per row */
#define FTILE (64*FQSTR*2)             /* 9216 B per 64x64 tile */
#define FSTAGE (4*FTILE)               /* Kh,Kl,Vh,Vl */
#define FLASH_SMEM (2*128*FQSTR*2 + 2*FSTAGE)  /* 110592 B */

__global__ __launch_bounds__(256, 1)
void flash_mma(const __nv_bfloat16* __restrict__ Qh_, const __nv_bfloat16* __restrict__ Ql_,
               const __nv_bfloat16* __restrict__ Kh_, const __nv_bfloat16* __restrict__ Kl_,
               const __nv_bfloat16* __restrict__ Vh_, const __nv_bfloat16* __restrict__ Vl_,
               __nv_bfloat16* __restrict__ AOh, __nv_bfloat16* __restrict__ AOl)
{
    extern __shared__ char smc[];
    const int qt  = (int)gridDim.x - 1 - (int)blockIdx.x;   // heavy tiles first
    const int h   = blockIdx.y, b = blockIdx.z;
    const int tid = threadIdx.x;
    const int lane = tid & 31, w = tid >> 5;
    const int qbase = qt*128;
    const int ktmax = 2*qt + 1;

    const uint32_t sb  = smem_u32(smc);
    const uint32_t uQh = sb;
    const uint32_t uQl = sb + 128*FQSTR*2;
    const uint32_t uKV = sb + 2*128*FQSTR*2;

    const __nv_bfloat16* qsrc[2]  = {Qh_, Ql_};
    const __nv_bfloat16* kvsrc[4] = {Kh_, Kl_, Vh_, Vl_};
    const size_t hofs = (size_t)h*64;

    auto load_kv = [&](int kt, int s) {
#pragma unroll
        for (int i = 0; i < 8; i++) {
            int id = tid + i*256;
            int a = id >> 9, r = (id >> 3) & 63, c = id & 7;
            const __nv_bfloat16* g = kvsrc[a] + (size_t)(b*SS + kt*64 + r)*DD + hofs + c*8;
            cp_async16(uKV + s*FSTAGE + a*FTILE + (uint32_t)(r*FQSTR + c*8)*2, g);
        }
    };

    // Q tile + KV(0)
#pragma unroll
    for (int i = 0; i < 8; i++) {
        int id = tid + i*256;
        int a = id >> 10, r = (id >> 3) & 127, c = id & 7;
        const __nv_bfloat16* g = qsrc[a] + (size_t)(b*SS + qbase + r)*DD + hofs + c*8;
        cp_async16((a ? uQl : uQh) + (uint32_t)(r*FQSTR + c*8)*2, g);
    }
    cp_commit();
    load_kv(0, 0);
    cp_commit();
    cp_wait<0>();
    __syncthreads();

    const int gid = lane >> 2, tig = lane & 3;
    const int qrow_off = ((lane>>3)&1)*8 + (lane&7);
    const int qd_off   = (lane>>4)*8;
    const int krow_off = (lane>>4)*8 + (lane&7);
    const int kd_off   = ((lane>>3)&1)*8;
    const int vrow_off = ((lane>>3)&1)*8 + (lane&7);
    const int vd_off   = (lane>>4)*8;

    // Q fragments (persistent)
    uint32_t qh[4][4], ql[4][4];
    {
        uint32_t ah = uQh + (uint32_t)((16*w + qrow_off)*FQSTR + qd_off)*2;
        uint32_t al = uQl + (uint32_t)((16*w + qrow_off)*FQSTR + qd_off)*2;
#pragma unroll
        for (int kk = 0; kk < 4; kk++) {
            ldm_x4(qh[kk], ah + kk*32);
            ldm_x4(ql[kk], al + kk*32);
        }
    }

    float m0 = -INFINITY, m1 = -INFINITY, l0 = 0.f, l1 = 0.f;
    float oacc[8][4];
#pragma unroll
    for (int nt = 0; nt < 8; nt++)
#pragma unroll
        for (int q = 0; q < 4; q++) oacc[nt][q] = 0.f;

    const int row0 = qbase + 16*w + gid;
    const int row1 = row0 + 8;

    for (int kt = 0; kt <= ktmax; kt++) {
        if (kt < ktmax) { load_kv(kt+1, (kt+1)&1); cp_commit(); }
        const uint32_t st = uKV + (kt&1)*FSTAGE;
        const bool active = (kt*64 <= qbase + 16*w + 15);
        if (active) {
            float sacc[8][4];
#pragma unroll
            for (int nt = 0; nt < 8; nt++)
#pragma unroll
                for (int q = 0; q < 4; q++) sacc[nt][q] = 0.f;

            // ---- S = Qh*Kh + Ql*Kh + Qh*Kl ----
#pragma unroll
            for (int kk = 0; kk < 4; kk++) {
                const uint32_t kb0 = st + (uint32_t)(krow_off*FQSTR + kd_off + 16*kk)*2;
                uint32_t kb[8][2];
#pragma unroll
                for (int p = 0; p < 4; p++) {
                    uint32_t r[4];
                    ldm_x4(r, kb0 + (uint32_t)(16*p*FQSTR)*2);
                    kb[2*p][0] = r[0]; kb[2*p][1] = r[1];
                    kb[2*p+1][0] = r[2]; kb[2*p+1][1] = r[3];
                }
#pragma unroll
                for (int nt = 0; nt < 8; nt++) mma_bf16(sacc[nt], qh[kk], kb[nt]);
#pragma unroll
                for (int nt = 0; nt < 8; nt++) mma_bf16(sacc[nt], ql[kk], kb[nt]);
                const uint32_t kl0 = kb0 + FTILE;
#pragma unroll
                for (int p = 0; p < 4; p++) {
                    uint32_t r[4];
                    ldm_x4(r, kl0 + (uint32_t)(16*p*FQSTR)*2);
                    kb[2*p][0] = r[0]; kb[2*p][1] = r[1];
                    kb[2*p+1][0] = r[2]; kb[2*p+1][1] = r[3];
                }
#pragma unroll
                for (int nt = 0; nt < 8; nt++) mma_bf16(sacc[nt], qh[kk], kb[nt]);
            }

            // ---- causal mask (only near-diagonal tiles) ----
            if (kt >= 2*qt) {
                const int colb = kt*64 + 2*tig;
#pragma unroll
                for (int nt = 0; nt < 8; nt++) {
                    int c0 = colb + 8*nt, c1 = c0 + 1;
                    if (c0 > row0) sacc[nt][0] = -1e10f;
                    if (c1 > row0) sacc[nt][1] = -1e10f;
                    if (c0 > row1) sacc[nt][2] = -1e10f;
                    if (c1 > row1) sacc[nt][3] = -1e10f;
                }
            }

            // ---- online softmax (register + shfl only) ----
            float rm0 = -INFINITY, rm1 = -INFINITY;
#pragma unroll
            for (int nt = 0; nt < 8; nt++) {
                rm0 = fmaxf(rm0, fmaxf(sacc[nt][0], sacc[nt][1]));
                rm1 = fmaxf(rm1, fmaxf(sacc[nt][2], sacc[nt][3]));
            }
            rm0 = warp_rmax(rm0); rm1 = warp_rmax(rm1);
            float mn0 = fmaxf(m0, rm0), mn1 = fmaxf(m1, rm1);
            float cr0 = __expf(m0 - mn0), cr1 = __expf(m1 - mn1);
            m0 = mn0; m1 = mn1;
            float ps0 = 0.f, ps1 = 0.f;
#pragma unroll
            for (int nt = 0; nt < 8; nt++) {
                float p0 = __expf(sacc[nt][0] - mn0);
                float p1 = __expf(sacc[nt][1] - mn0);
                float p2 = __expf(sacc[nt][2] - mn1);
                float p3 = __expf(sacc[nt][3] - mn1);
                sacc[nt][0] = p0; sacc[nt][1] = p1; sacc[nt][2] = p2; sacc[nt][3] = p3;
                ps0 += p0 + p1; ps1 += p2 + p3;
            }
            ps0 = warp_rsum(ps0); ps1 = warp_rsum(ps1);
            l0 = l0*cr0 + ps0; l1 = l1*cr1 + ps1;
#pragma unroll
            for (int nt = 0; nt < 8; nt++) {
                oacc[nt][0] *= cr0; oacc[nt][1] *= cr0;
                oacc[nt][2] *= cr1; oacc[nt][3] *= cr1;
            }

            // ---- O += Ph*Vh + Pl*Vh + Ph*Vl ----
#pragma unroll
            for (int kk = 0; kk < 4; kk++) {
                uint32_t pah[4], pal[4];
#pragma unroll
                for (int jj = 0; jj < 2; jj++) {
                    const float* s4 = sacc[2*kk + jj];
                    uint32_t h01 = packbf(s4[0], s4[1]);
                    uint32_t h23 = packbf(s4[2], s4[3]);
                    pah[2*jj]   = h01;
                    pah[2*jj+1] = h23;
                    pal[2*jj]   = packbf(s4[0] - bflo(h01), s4[1] - bfhi(h01));
                    pal[2*jj+1] = packbf(s4[2] - bflo(h23), s4[3] - bfhi(h23));
                }
                const uint32_t vb0 = st + 2*FTILE + (uint32_t)((16*kk + vrow_off)*FQSTR + vd_off)*2;
                uint32_t vb[8][2];
#pragma unroll
                for (int p = 0; p < 4; p++) {
                    uint32_t r[4];
                    ldm_x4_t(r, vb0 + (uint32_t)(16*p)*2);
                    vb[2*p][0] = r[0]; vb[2*p][1] = r[1];
                    vb[2*p+1][0] = r[2]; vb[2*p+1][1] = r[3];
                }
#pragma unroll
                for (int nt = 0; nt < 8; nt++) mma_bf16(oacc[nt], pah, vb[nt]);
#pragma unroll
                for (int nt = 0; nt < 8; nt++) mma_bf16(oacc[nt], pal, vb[nt]);
                const uint32_t vl0 = vb0 + FTILE;
#pragma unroll
                for (int p = 0; p < 4; p++) {
                    uint32_t r[4];
                    ldm_x4_t(r, vl0 + (uint32_t)(16*p)*2);
                    vb[2*p][0] = r[0]; vb[2*p][1] = r[1];
                    vb[2*p+1][0] = r[2]; vb[2*p+1][1] = r[3];
                }
#pragma unroll
                for (int nt = 0; nt < 8; nt++) mma_bf16(oacc[nt], pah, vb[nt]);
            }
        }
        if (kt < ktmax) { cp_wait<0>(); __syncthreads(); }
    }

    // ---- epilogue: normalize + split to bf16 hi/lo ----
    const float inv0 = 1.f / l0, inv1 = 1.f / l1;
    const size_t r0g = (size_t)(b*SS + row0);
    const size_t r1g = (size_t)(b*SS + row1);
#pragma unroll
    for (int nt = 0; nt < 8; nt++) {
        const size_t col = hofs + 8*nt + 2*tig;
        float x0 = oacc[nt][0]*inv0, x1 = oacc[nt][1]*inv0;
        float x2 = oacc[nt][2]*inv1, x3 = oacc[nt][3]*inv1;
        uint32_t h01 = packbf(x0, x1), h23 = packbf(x2, x3);
        uint32_t l01 = packbf(x0 - bflo(h01), x1 - bfhi(h01));
        uint32_t l23 = packbf(x2 - bflo(h23), x3 - bfhi(h23));
        *(uint32_t*)(AOh + r0g*DD + col) = h01;
        *(uint32_t*)(AOl + r0g*DD + col) = l01;
        *(uint32_t*)(AOh + r1g*DD + col) = h23;
        *(uint32_t*)(AOl + r1g*DD + col) = l23;
    }
}

// ---------------------------------------------------------------------------
extern "C" void kernel_launch(void* const* d_in, const int* in_sizes, int n_in,
                              void* d_out, int out_size)
{
    (void)in_sizes; (void)n_in; (void)out_size;
    const float* X  = (const float*)d_in[0];
    const float* Wq = (const float*)d_in[1];
    const float* Wk = (const float*)d_in[2];
    const float* Wv = (const float*)d_in[3];
    const float* Wo = (const float*)d_in[4];
    float* out = (float*)d_out;

    __nv_bfloat16 *Xh, *Xl, *Qh, *Ql, *Kh, *Kl, *Vh, *Vl, *AOh, *AOl;
    __nv_bfloat16 *Wqh, *Wql, *Wkh, *Wkl, *Wvh, *Wvl, *Woh, *Wol;
    cudaGetSymbolAddress((void**)&Xh,  g_Xh);
    cudaGetSymbolAddress((void**)&Xl,  g_Xl);
    cudaGetSymbolAddress((void**)&Qh,  g_Qh);
    cudaGetSymbolAddress((void**)&Ql,  g_Ql);
    cudaGetSymbolAddress((void**)&Kh,  g_Kh);
    cudaGetSymbolAddress((void**)&Kl,  g_Kl);
    cudaGetSymbolAddress((void**)&Vh,  g_Vh);
    cudaGetSymbolAddress((void**)&Vl,  g_Vl);
    cudaGetSymbolAddress((void**)&AOh, g_AOh);
    cudaGetSymbolAddress((void**)&AOl, g_AOl);
    cudaGetSymbolAddress((void**)&Wqh, g_Wqh);
    cudaGetSymbolAddress((void**)&Wql, g_Wql);
    cudaGetSymbolAddress((void**)&Wkh, g_Wkh);
    cudaGetSymbolAddress((void**)&Wkl, g_Wkl);
    cudaGetSymbolAddress((void**)&Wvh, g_Wvh);
    cudaGetSymbolAddress((void**)&Wvl, g_Wvl);
    cudaGetSymbolAddress((void**)&Woh, g_Woh);
    cudaGetSymbolAddress((void**)&Wol, g_Wol);

    cudaFuncSetAttribute(gemm_bf16x2<true>,  cudaFuncAttributeMaxDynamicSharedMemorySize, GEMM_SMEM);
    cudaFuncSetAttribute(gemm_bf16x2<false>, cudaFuncAttributeMaxDynamicSharedMemorySize, GEMM_SMEM);
    cudaFuncSetAttribute(flash_mma, cudaFuncAttributeMaxDynamicSharedMemorySize, FLASH_SMEM);

    split_bf16<<<512, 256>>>(X,  Xh,  Xl,  GM*DD/4);
    split_bf16<<<256, 256>>>(Wq, Wqh, Wql, DD*DD/4);
    split_bf16<<<256, 256>>>(Wk, Wkh, Wkl, DD*DD/4);
    split_bf16<<<256, 256>>>(Wv, Wvh, Wvl, DD*DD/4);
    split_bf16<<<256, 256>>>(Wo, Woh, Wol, DD*DD/4);

    dim3 gg(GN/128, GM/128);   // (8, 32)
    gemm_bf16x2<true><<<gg, 256, GEMM_SMEM>>>(Xh, Xl, Wqh, Wql, nullptr, Qh, Ql, 0.125f);
    gemm_bf16x2<true><<<gg, 256, GEMM_SMEM>>>(Xh, Xl, Wkh, Wkl, nullptr, Kh, Kl, 1.0f);
    gemm_bf16x2<true><<<gg, 256, GEMM_SMEM>>>(Xh, Xl, Wvh, Wvl, nullptr, Vh, Vl, 1.0f);

    flash_mma<<<dim3(SS/128, HH, BB), 256, FLASH_SMEM>>>(Qh, Ql, Kh, Kl, Vh, Vl, AOh, AOl);

    gemm_bf16x2<false><<<gg, 256, GEMM_SMEM>>>(AOh, AOl, Woh, Wol, out, nullptr, nullptr, 1.0f);
}

// round 6
// speedup vs baseline: 2.7415x; 1.0337x over previous
#include <cuda_runtime.h>
#include <cuda_bf16.h>
#include <math.h>
#include <stdint.h>

#define BB 2
#define SS 2048
#define DD 1024
#define HH 16
#define GM (BB*SS)   /* 4096 */
#define GN DD
#define GK DD

// ---------------- scratch (allocation-free) ----------------
__device__ __nv_bfloat16 g_Xh[GM*DD],  g_Xl[GM*DD];
__device__ __nv_bfloat16 g_Qh[GM*DD],  g_Ql[GM*DD];
__device__ __nv_bfloat16 g_Kh[GM*DD],  g_Kl[GM*DD];
__device__ __nv_bfloat16 g_Vh[GM*DD],  g_Vl[GM*DD];
__device__ __nv_bfloat16 g_AOh[GM*DD], g_AOl[GM*DD];
__device__ __nv_bfloat16 g_Wqh[DD*DD], g_Wql[DD*DD];
__device__ __nv_bfloat16 g_Wkh[DD*DD], g_Wkl[DD*DD];
__device__ __nv_bfloat16 g_Wvh[DD*DD], g_Wvl[DD*DD];
__device__ __nv_bfloat16 g_Woh[DD*DD], g_Wol[DD*DD];

// ---------------- helpers ----------------
__device__ __forceinline__ uint32_t smem_u32(const void* p) {
    return (uint32_t)__cvta_generic_to_shared(p);
}
__device__ __forceinline__ void cp_async16(uint32_t dst, const void* src) {
    asm volatile("cp.async.cg.shared.global [%0], [%1], 16;" :: "r"(dst), "l"(src) : "memory");
}
__device__ __forceinline__ void cp_commit() {
    asm volatile("cp.async.commit_group;" ::: "memory");
}
template<int N>
__device__ __forceinline__ void cp_wait() {
    asm volatile("cp.async.wait_group %0;" :: "n"(N) : "memory");
}
__device__ __forceinline__ void ldm_x4(uint32_t* r, uint32_t addr) {
    asm volatile("ldmatrix.sync.aligned.m8n8.x4.shared.b16 {%0,%1,%2,%3}, [%4];"
                 : "=r"(r[0]), "=r"(r[1]), "=r"(r[2]), "=r"(r[3]) : "r"(addr));
}
__device__ __forceinline__ void ldm_x4_t(uint32_t* r, uint32_t addr) {
    asm volatile("ldmatrix.sync.aligned.m8n8.x4.trans.shared.b16 {%0,%1,%2,%3}, [%4];"
                 : "=r"(r[0]), "=r"(r[1]), "=r"(r[2]), "=r"(r[3]) : "r"(addr));
}
__device__ __forceinline__ void mma_bf16(float* c, const uint32_t* a, const uint32_t* b) {
    asm volatile("mma.sync.aligned.m16n8k16.row.col.f32.bf16.bf16.f32 "
                 "{%0,%1,%2,%3}, {%4,%5,%6,%7}, {%8,%9}, {%0,%1,%2,%3};"
                 : "+f"(c[0]), "+f"(c[1]), "+f"(c[2]), "+f"(c[3])
                 : "r"(a[0]), "r"(a[1]), "r"(a[2]), "r"(a[3]), "r"(b[0]), "r"(b[1]));
}
__device__ __forceinline__ uint32_t packbf(float lo, float hi) {
    uint32_t r; asm("cvt.rn.bf16x2.f32 %0, %1, %2;" : "=r"(r) : "f"(hi), "f"(lo)); return r;
}
__device__ __forceinline__ float bflo(uint32_t r) { return __uint_as_float(r << 16); }
__device__ __forceinline__ float bfhi(uint32_t r) { return __uint_as_float(r & 0xffff0000u); }
__device__ __forceinline__ float warp_rmax(float x) {
    x = fmaxf(x, __shfl_xor_sync(0xffffffffu, x, 1));
    x = fmaxf(x, __shfl_xor_sync(0xffffffffu, x, 2));
    return x;
}
__device__ __forceinline__ float warp_rsum(float x) {
    x += __shfl_xor_sync(0xffffffffu, x, 1);
    x += __shfl_xor_sync(0xffffffffu, x, 2);
    return x;
}

// ---------------- split fp32 -> bf16 hi/lo ----------------
__global__ void split_bf16(const float* __restrict__ in, __nv_bfloat16* __restrict__ hi,
                           __nv_bfloat16* __restrict__ lo, int n4)
{
    int i = blockIdx.x*blockDim.x + threadIdx.x;
    int stride = gridDim.x*blockDim.x;
    const float4* in4 = (const float4*)in;
    uint32_t* h2 = (uint32_t*)hi;
    uint32_t* l2 = (uint32_t*)lo;
    for (; i < n4; i += stride) {
        float4 v = in4[i];
        uint32_t h01 = packbf(v.x, v.y), h23 = packbf(v.z, v.w);
        uint32_t l01 = packbf(v.x - bflo(h01), v.y - bfhi(h01));
        uint32_t l23 = packbf(v.z - bflo(h23), v.w - bfhi(h23));
        h2[i*2] = h01; h2[i*2+1] = h23;
        l2[i*2] = l01; l2[i*2+1] = l23;
    }
}

// ---------------- bf16x2 GEMM on mma.sync: C = alpha * (A @ B^T) ----------------
// 128x128 tile, K-chunk 64, 3-stage cp.async pipeline, fragment-reuse inner loop.
#define KCH 64
#define NCH (GK/KCH)
#define SRE 72
#define SRB (SRE*2)
#define TILE_B (128*SRB)
#define STAGE_B (4*TILE_B)          /* 73728 */
#define GEMM_SMEM (3*STAGE_B)       /* 221184 */

template<bool SPLIT>
__global__ __launch_bounds__(256, 1)
void gemm_bf16x2(const __nv_bfloat16* __restrict__ Ah, const __nv_bfloat16* __restrict__ Al,
                 const __nv_bfloat16* __restrict__ Bh, const __nv_bfloat16* __restrict__ Bl,
                 float* __restrict__ Cf, __nv_bfloat16* __restrict__ Chi,
                 __nv_bfloat16* __restrict__ Clo, float alpha)
{
    extern __shared__ char smem[];
    const uint32_t sb = smem_u32(smem);
    const int tid  = threadIdx.x;
    const int lane = tid & 31;
    const int warp = tid >> 5;
    const int wm   = warp & 3;
    const int wn   = warp >> 2;
    const int cRow = blockIdx.y << 7;
    const int cCol = blockIdx.x << 7;

    const __nv_bfloat16* gsrc[4];
    gsrc[0] = Ah + (size_t)cRow*GK;
    gsrc[1] = Al + (size_t)cRow*GK;
    gsrc[2] = Bh + (size_t)cCol*GK;
    gsrc[3] = Bl + (size_t)cCol*GK;

    const int ldRow = tid >> 3;
    const int ldCol = tid & 7;

    const uint32_t aOff = (uint32_t)((lane & 15)*SRB + (lane >> 4)*16 + wm*32*SRB);
    const uint32_t bOff = (uint32_t)(((lane & 7) + ((lane >> 4) << 3))*SRB
                                     + ((lane >> 3) & 1)*16 + wn*64*SRB);

    float acc[2][8][4];
#pragma unroll
    for (int mt = 0; mt < 2; mt++)
#pragma unroll
        for (int nt = 0; nt < 8; nt++)
#pragma unroll
            for (int q = 0; q < 4; q++) acc[mt][nt][q] = 0.f;

    auto issue_chunk = [&](int j, int s) {
        const uint32_t st = sb + (uint32_t)s*STAGE_B;
        const int k0 = j*KCH;
#pragma unroll
        for (int t = 0; t < 4; t++)
#pragma unroll
            for (int i = 0; i < 4; i++) {
                int row = ldRow + i*32;
                cp_async16(st + t*TILE_B + row*SRB + ldCol*16,
                           gsrc[t] + (size_t)row*GK + k0 + ldCol*8);
            }
        cp_commit();
    };

    issue_chunk(0, 0);
    issue_chunk(1, 1);

    for (int j = 0; j < NCH; j++) {
        if (j + 2 < NCH) issue_chunk(j + 2, (j + 2) % 3);
        if (j + 2 < NCH)      cp_wait<2>();
        else if (j + 1 < NCH) cp_wait<1>();
        else                  cp_wait<0>();
        __syncthreads();

        const uint32_t stg = sb + (uint32_t)(j % 3)*STAGE_B;
        const uint32_t aBH = stg + aOff;
        const uint32_t aBL = stg + TILE_B + aOff;
        const uint32_t bBH = stg + 2*TILE_B + bOff;
        const uint32_t bBL = stg + 3*TILE_B + bOff;
#pragma unroll
        for (int k16 = 0; k16 < 4; k16++) {
            uint32_t ah2[2][4], al2[2][4], bh2[4][4], bl2[4][4];
            ldm_x4(ah2[0], aBH + k16*32);
            ldm_x4(ah2[1], aBH + k16*32 + 16*SRB);
            ldm_x4(al2[0], aBL + k16*32);
            ldm_x4(al2[1], aBL + k16*32 + 16*SRB);
#pragma unroll
            for (int ng = 0; ng < 4; ng++) {
                ldm_x4(bh2[ng], bBH + k16*32 + ng*16*SRB);
                ldm_x4(bl2[ng], bBL + k16*32 + ng*16*SRB);
            }
#pragma unroll
            for (int mt = 0; mt < 2; mt++)
#pragma unroll
                for (int ng = 0; ng < 4; ng++) {
                    mma_bf16(acc[mt][2*ng+0], ah2[mt], &bh2[ng][0]);
                    mma_bf16(acc[mt][2*ng+1], ah2[mt], &bh2[ng][2]);
                    mma_bf16(acc[mt][2*ng+0], al2[mt], &bh2[ng][0]);
                    mma_bf16(acc[mt][2*ng+1], al2[mt], &bh2[ng][2]);
                    mma_bf16(acc[mt][2*ng+0], ah2[mt], &bl2[ng][0]);
                    mma_bf16(acc[mt][2*ng+1], ah2[mt], &bl2[ng][2]);
                }
        }
        __syncthreads();
    }

    const int gid = lane >> 2, tig = lane & 3;
#pragma unroll
    for (int mt = 0; mt < 2; mt++) {
        const int m0 = cRow + wm*32 + mt*16 + gid;
#pragma unroll
        for (int nt = 0; nt < 8; nt++) {
            const int n = cCol + wn*64 + nt*8 + tig*2;
            float v0 = acc[mt][nt][0]*alpha, v1 = acc[mt][nt][1]*alpha;
            float v2 = acc[mt][nt][2]*alpha, v3 = acc[mt][nt][3]*alpha;
            if (SPLIT) {
                uint32_t h01 = packbf(v0, v1), h23 = packbf(v2, v3);
                uint32_t l01 = packbf(v0 - bflo(h01), v1 - bfhi(h01));
                uint32_t l23 = packbf(v2 - bflo(h23), v3 - bfhi(h23));
                *(uint32_t*)(Chi + (size_t)m0*GN + n)     = h01;
                *(uint32_t*)(Clo + (size_t)m0*GN + n)     = l01;
                *(uint32_t*)(Chi + (size_t)(m0+8)*GN + n) = h23;
                *(uint32_t*)(Clo + (size_t)(m0+8)*GN + n) = l23;
            } else {
                float2 a0 = {v0, v1}, a1 = {v2, v3};
                *(float2*)(Cf + (size_t)m0*GN + n)     = a0;
                *(float2*)(Cf + (size_t)(m0+8)*GN + n) = a1;
            }
        }
    }
}

// ---------------------------------------------------------------------------
// Flash attention on mma.sync, causal, bf16x2. 3-stage KV pipeline.
// ---------------------------------------------------------------------------
#define FQSTR 72
#define FTILE (64*FQSTR*2)
#define FSTAGE (4*FTILE)                         /* 36864 */
#define FLASH_SMEM (2*128*FQSTR*2 + 3*FSTAGE)    /* 147456 */

__global__ __launch_bounds__(256, 1)
void flash_mma(const __nv_bfloat16* __restrict__ Qh_, const __nv_bfloat16* __restrict__ Ql_,
               const __nv_bfloat16* __restrict__ Kh_, const __nv_bfloat16* __restrict__ Kl_,
               const __nv_bfloat16* __restrict__ Vh_, const __nv_bfloat16* __restrict__ Vl_,
               __nv_bfloat16* __restrict__ AOh, __nv_bfloat16* __restrict__ AOl)
{
    extern __shared__ char smc[];
    const int qt  = (int)gridDim.x - 1 - (int)blockIdx.x;
    const int h   = blockIdx.y, b = blockIdx.z;
    const int tid = threadIdx.x;
    const int lane = tid & 31, w = tid >> 5;
    const int qbase = qt*128;
    const int ktmax = 2*qt + 1;

    const uint32_t sb  = smem_u32(smc);
    const uint32_t uQh = sb;
    const uint32_t uQl = sb + 128*FQSTR*2;
    const uint32_t uKV = sb + 2*128*FQSTR*2;

    const __nv_bfloat16* qsrc[2]  = {Qh_, Ql_};
    const __nv_bfloat16* kvsrc[4] = {Kh_, Kl_, Vh_, Vl_};
    const size_t hofs = (size_t)h*64;

    auto load_kv = [&](int kt, int s) {
#pragma unroll
        for (int i = 0; i < 8; i++) {
            int id = tid + i*256;
            int a = id >> 9, r = (id >> 3) & 63, c = id & 7;
            const __nv_bfloat16* g = kvsrc[a] + (size_t)(b*SS + kt*64 + r)*DD + hofs + c*8;
            cp_async16(uKV + s*FSTAGE + a*FTILE + (uint32_t)(r*FQSTR + c*8)*2, g);
        }
    };

    // group 0: Q tile + KV0
#pragma unroll
    for (int i = 0; i < 8; i++) {
        int id = tid + i*256;
        int a = id >> 10, r = (id >> 3) & 127, c = id & 7;
        const __nv_bfloat16* g = qsrc[a] + (size_t)(b*SS + qbase + r)*DD + hofs + c*8;
        cp_async16((a ? uQl : uQh) + (uint32_t)(r*FQSTR + c*8)*2, g);
    }
    load_kv(0, 0);
    cp_commit();
    // group 1: KV1 (ktmax >= 1 always)
    load_kv(1, 1);
    cp_commit();

    const int gid = lane >> 2, tig = lane & 3;
    const int qrow_off = ((lane>>3)&1)*8 + (lane&7);
    const int qd_off   = (lane>>4)*8;
    const int krow_off = (lane>>4)*8 + (lane&7);
    const int kd_off   = ((lane>>3)&1)*8;
    const int vrow_off = ((lane>>3)&1)*8 + (lane&7);
    const int vd_off   = (lane>>4)*8;

    uint32_t qh[4][4], ql[4][4];

    float m0 = -INFINITY, m1 = -INFINITY, l0 = 0.f, l1 = 0.f;
    float oacc[8][4];
#pragma unroll
    for (int nt = 0; nt < 8; nt++)
#pragma unroll
        for (int q = 0; q < 4; q++) oacc[nt][q] = 0.f;

    const int row0 = qbase + 16*w + gid;
    const int row1 = row0 + 8;

    for (int kt = 0; kt <= ktmax; kt++) {
        if (kt + 2 <= ktmax) { load_kv(kt + 2, (kt + 2) % 3); cp_commit(); }
        if (kt + 2 <= ktmax)      cp_wait<2>();
        else if (kt + 1 <= ktmax) cp_wait<1>();
        else                      cp_wait<0>();
        __syncthreads();

        if (kt == 0) {
            uint32_t ah = uQh + (uint32_t)((16*w + qrow_off)*FQSTR + qd_off)*2;
            uint32_t al = uQl + (uint32_t)((16*w + qrow_off)*FQSTR + qd_off)*2;
#pragma unroll
            for (int kk = 0; kk < 4; kk++) {
                ldm_x4(qh[kk], ah + kk*32);
                ldm_x4(ql[kk], al + kk*32);
            }
        }

        const uint32_t st = uKV + (uint32_t)(kt % 3)*FSTAGE;
        const bool active = (kt*64 <= qbase + 16*w + 15);
        if (active) {
            float sacc[8][4];
#pragma unroll
            for (int nt = 0; nt < 8; nt++)
#pragma unroll
                for (int q = 0; q < 4; q++) sacc[nt][q] = 0.f;

            // ---- S = Qh*Kh + Ql*Kh + Qh*Kl ----
#pragma unroll
            for (int kk = 0; kk < 4; kk++) {
                const uint32_t kb0 = st + (uint32_t)(krow_off*FQSTR + kd_off + 16*kk)*2;
                uint32_t kb[8][2], kl[8][2];
#pragma unroll
                for (int p = 0; p < 4; p++) {
                    uint32_t r[4];
                    ldm_x4(r, kb0 + (uint32_t)(16*p*FQSTR)*2);
                    kb[2*p][0] = r[0]; kb[2*p][1] = r[1];
                    kb[2*p+1][0] = r[2]; kb[2*p+1][1] = r[3];
                    ldm_x4(r, kb0 + FTILE + (uint32_t)(16*p*FQSTR)*2);
                    kl[2*p][0] = r[0]; kl[2*p][1] = r[1];
                    kl[2*p+1][0] = r[2]; kl[2*p+1][1] = r[3];
                }
#pragma unroll
                for (int nt = 0; nt < 8; nt++) {
                    mma_bf16(sacc[nt], qh[kk], kb[nt]);
                    mma_bf16(sacc[nt], ql[kk], kb[nt]);
                    mma_bf16(sacc[nt], qh[kk], kl[nt]);
                }
            }

            // ---- causal mask ----
            if (kt >= 2*qt) {
                const int colb = kt*64 + 2*tig;
#pragma unroll
                for (int nt = 0; nt < 8; nt++) {
                    int c0 = colb + 8*nt, c1 = c0 + 1;
                    if (c0 > row0) sacc[nt][0] = -1e10f;
                    if (c1 > row0) sacc[nt][1] = -1e10f;
                    if (c0 > row1) sacc[nt][2] = -1e10f;
                    if (c1 > row1) sacc[nt][3] = -1e10f;
                }
            }

            // ---- online softmax ----
            float rm0 = -INFINITY, rm1 = -INFINITY;
#pragma unroll
            for (int nt = 0; nt < 8; nt++) {
                rm0 = fmaxf(rm0, fmaxf(sacc[nt][0], sacc[nt][1]));
                rm1 = fmaxf(rm1, fmaxf(sacc[nt][2], sacc[nt][3]));
            }
            rm0 = warp_rmax(rm0); rm1 = warp_rmax(rm1);
            float mn0 = fmaxf(m0, rm0), mn1 = fmaxf(m1, rm1);
            float cr0 = __expf(m0 - mn0), cr1 = __expf(m1 - mn1);
            m0 = mn0; m1 = mn1;
            float ps0 = 0.f, ps1 = 0.f;
#pragma unroll
            for (int nt = 0; nt < 8; nt++) {
                float p0 = __expf(sacc[nt][0] - mn0);
                float p1 = __expf(sacc[nt][1] - mn0);
                float p2 = __expf(sacc[nt][2] - mn1);
                float p3 = __expf(sacc[nt][3] - mn1);
                sacc[nt][0] = p0; sacc[nt][1] = p1; sacc[nt][2] = p2; sacc[nt][3] = p3;
                ps0 += p0 + p1; ps1 += p2 + p3;
            }
            ps0 = warp_rsum(ps0); ps1 = warp_rsum(ps1);
            l0 = l0*cr0 + ps0; l1 = l1*cr1 + ps1;
#pragma unroll
            for (int nt = 0; nt < 8; nt++) {
                oacc[nt][0] *= cr0; oacc[nt][1] *= cr0;
                oacc[nt][2] *= cr1; oacc[nt][3] *= cr1;
            }

            // ---- O += Ph*Vh + Pl*Vh + Ph*Vl ----
#pragma unroll
            for (int kk = 0; kk < 4; kk++) {
                uint32_t pah[4], pal[4];
#pragma unroll
                for (int jj = 0; jj < 2; jj++) {
                    const float* s4 = sacc[2*kk + jj];
                    uint32_t h01 = packbf(s4[0], s4[1]);
                    uint32_t h23 = packbf(s4[2], s4[3]);
                    pah[2*jj]   = h01;
                    pah[2*jj+1] = h23;
                    pal[2*jj]   = packbf(s4[0] - bflo(h01), s4[1] - bfhi(h01));
                    pal[2*jj+1] = packbf(s4[2] - bflo(h23), s4[3] - bfhi(h23));
                }
                const uint32_t vb0 = st + 2*FTILE + (uint32_t)((16*kk + vrow_off)*FQSTR + vd_off)*2;
                uint32_t vb[8][2], vl[8][2];
#pragma unroll
                for (int p = 0; p < 4; p++) {
                    uint32_t r[4];
                    ldm_x4_t(r, vb0 + (uint32_t)(16*p)*2);
                    vb[2*p][0] = r[0]; vb[2*p][1] = r[1];
                    vb[2*p+1][0] = r[2]; vb[2*p+1][1] = r[3];
                    ldm_x4_t(r, vb0 + FTILE + (uint32_t)(16*p)*2);
                    vl[2*p][0] = r[0]; vl[2*p][1] = r[1];
                    vl[2*p+1][0] = r[2]; vl[2*p+1][1] = r[3];
                }
#pragma unroll
                for (int nt = 0; nt < 8; nt++) {
                    mma_bf16(oacc[nt], pah, vb[nt]);
                    mma_bf16(oacc[nt], pal, vb[nt]);
                    mma_bf16(oacc[nt], pah, vl[nt]);
                }
            }
        }
        __syncthreads();
    }

    // ---- epilogue ----
    const float inv0 = 1.f / l0, inv1 = 1.f / l1;
    const size_t r0g = (size_t)(b*SS + row0);
    const size_t r1g = (size_t)(b*SS + row1);
#pragma unroll
    for (int nt = 0; nt < 8; nt++) {
        const size_t col = hofs + 8*nt + 2*tig;
        float x0 = oacc[nt][0]*inv0, x1 = oacc[nt][1]*inv0;
        float x2 = oacc[nt][2]*inv1, x3 = oacc[nt][3]*inv1;
        uint32_t h01 = packbf(x0, x1), h23 = packbf(x2, x3);
        uint32_t l01 = packbf(x0 - bflo(h01), x1 - bfhi(h01));
        uint32_t l23 = packbf(x2 - bflo(h23), x3 - bfhi(h23));
        *(uint32_t*)(AOh + r0g*DD + col) = h01;
        *(uint32_t*)(AOl + r0g*DD + col) = l01;
        *(uint32_t*)(AOh + r1g*DD + col) = h23;
        *(uint32_t*)(AOl + r1g*DD + col) = l23;
    }
}

// ---------------------------------------------------------------------------
extern "C" void kernel_launch(void* const* d_in, const int* in_sizes, int n_in,
                              void* d_out, int out_size)
{
    (void)in_sizes; (void)n_in; (void)out_size;
    const float* X  = (const float*)d_in[0];
    const float* Wq = (const float*)d_in[1];
    const float* Wk = (const float*)d_in[2];
    const float* Wv = (const float*)d_in[3];
    const float* Wo = (const float*)d_in[4];
    float* out = (float*)d_out;

    __nv_bfloat16 *Xh, *Xl, *Qh, *Ql, *Kh, *Kl, *Vh, *Vl, *AOh, *AOl;
    __nv_bfloat16 *Wqh, *Wql, *Wkh, *Wkl, *Wvh, *Wvl, *Woh, *Wol;
    cudaGetSymbolAddress((void**)&Xh,  g_Xh);
    cudaGetSymbolAddress((void**)&Xl,  g_Xl);
    cudaGetSymbolAddress((void**)&Qh,  g_Qh);
    cudaGetSymbolAddress((void**)&Ql,  g_Ql);
    cudaGetSymbolAddress((void**)&Kh,  g_Kh);
    cudaGetSymbolAddress((void**)&Kl,  g_Kl);
    cudaGetSymbolAddress((void**)&Vh,  g_Vh);
    cudaGetSymbolAddress((void**)&Vl,  g_Vl);
    cudaGetSymbolAddress((void**)&AOh, g_AOh);
    cudaGetSymbolAddress((void**)&AOl, g_AOl);
    cudaGetSymbolAddress((void**)&Wqh, g_Wqh);
    cudaGetSymbolAddress((void**)&Wql, g_Wql);
    cudaGetSymbolAddress((void**)&Wkh, g_Wkh);
    cudaGetSymbolAddress((void**)&Wkl, g_Wkl);
    cudaGetSymbolAddress((void**)&Wvh, g_Wvh);
    cudaGetSymbolAddress((void**)&Wvl, g_Wvl);
    cudaGetSymbolAddress((void**)&Woh, g_Woh);
    cudaGetSymbolAddress((void**)&Wol, g_Wol);

    cudaFuncSetAttribute(gemm_bf16x2<true>,  cudaFuncAttributeMaxDynamicSharedMemorySize, GEMM_SMEM);
    cudaFuncSetAttribute(gemm_bf16x2<false>, cudaFuncAttributeMaxDynamicSharedMemorySize, GEMM_SMEM);
    cudaFuncSetAttribute(flash_mma, cudaFuncAttributeMaxDynamicSharedMemorySize, FLASH_SMEM);

    split_bf16<<<512, 256>>>(X,  Xh,  Xl,  GM*DD/4);
    split_bf16<<<256, 256>>>(Wq, Wqh, Wql, DD*DD/4);
    split_bf16<<<256, 256>>>(Wk, Wkh, Wkl, DD*DD/4);
    split_bf16<<<256, 256>>>(Wv, Wvh, Wvl, DD*DD/4);
    split_bf16<<<256, 256>>>(Wo, Woh, Wol, DD*DD/4);

    dim3 gg(GN/128, GM/128);   // (8, 32)
    gemm_bf16x2<true><<<gg, 256, GEMM_SMEM>>>(Xh, Xl, Wqh, Wql, nullptr, Qh, Ql, 0.125f);
    gemm_bf16x2<true><<<gg, 256, GEMM_SMEM>>>(Xh, Xl, Wkh, Wkl, nullptr, Kh, Kl, 1.0f);
    gemm_bf16x2<true><<<gg, 256, GEMM_SMEM>>>(Xh, Xl, Wvh, Wvl, nullptr, Vh, Vl, 1.0f);

    flash_mma<<<dim3(SS/128, HH, BB), 256, FLASH_SMEM>>>(Qh, Ql, Kh, Kl, Vh, Vl, AOh, AOl);

    gemm_bf16x2<false><<<gg, 256, GEMM_SMEM>>>(AOh, AOl, Woh, Wol, out, nullptr, nullptr, 1.0f);
}